// round 13
// baseline (speedup 1.0000x reference)
#include <cuda_runtime.h>
#include <cstdint>

typedef unsigned long long ull;

#define B_   1024
#define T_   1024
#define H_   128
#define C_   6
#define BPC  8            // batches per CTA
#define NCTA (B_/BPC)     // 128
#define NTHR 384          // 8 gate warps (256) + 4 head warps (128)

// ---------------- packed transposed weights (device globals) ---------------
__device__ float2 g_wrz[H_*H_];    // [k][j] = (whh_r[j][k], whh_z[j][k])
__device__ float  g_wn [H_*H_];    // [k][j] = whh_n[j][k]
__device__ float  g_w1T[H_*H_];    // [k][j] = w1[j][k]      (head stream)
__device__ float  g_wu1T[H_*64];   // [k][u] = wu1[u][k]     (head stream)
__device__ float2 g_pIrz[12*H_];   // [k][j] = (wih_r, wih_z)[j][k]
__device__ float  g_pIn [12*H_];   // [k][j] = wih_n[j][k]

// ---------------- f32x2 helpers --------------------------------------------
__device__ __forceinline__ ull pk2(float a, float b){
    ull r; asm("mov.b64 %0, {%1,%2};" : "=l"(r) : "f"(a), "f"(b)); return r;
}
__device__ __forceinline__ void fma2(ull& d, ull a, ull b){
    asm("fma.rn.f32x2 %0, %1, %2, %3;" : "=l"(d) : "l"(a), "l"(b), "l"(d));
}
__device__ __forceinline__ void add2(ull& d, ull a){
    asm("add.rn.f32x2 %0, %1, %2;" : "=l"(d) : "l"(d), "l"(a));
}
__device__ __forceinline__ float2 up2(ull v){
    float2 r; asm("mov.b64 {%0,%1}, %2;" : "=f"(r.x), "=f"(r.y) : "l"(v)); return r;
}
__device__ __forceinline__ float sigf(float x){
    return __fdividef(1.f, 1.f + __expf(-x));
}
__device__ __forceinline__ float tanhfast(float x){
    float e = __expf(-2.f * fabsf(x));
    float t = __fdividef(1.f - e, 1.f + e);
    return copysignf(t, x);
}
#define BARG() asm volatile("bar.sync 1, 256;" ::: "memory")   // gate warps only
#define BARH() asm volatile("bar.sync 2, 128;" ::: "memory")   // head warps only

// ---------------- weight pack pre-pass -------------------------------------
__global__ void pack_kernel(const float* __restrict__ w_ih, const float* __restrict__ w_hh,
                            const float* __restrict__ w1,   const float* __restrict__ wu1){
    int idx = blockIdx.x * blockDim.x + threadIdx.x;   // 0..16383
    int k = idx >> 7, j = idx & 127;
    g_wrz[idx] = make_float2(w_hh[j*H_ + k], w_hh[(j+H_)*H_ + k]);
    g_wn[idx]  = w_hh[(j+2*H_)*H_ + k];
    g_w1T[idx] = w1[j*H_ + k];
    if (j < 64)  g_wu1T[k*64 + j] = wu1[j*H_ + k];
    if (k < 12) {
        g_pIrz[k*H_ + j] = make_float2(w_ih[j*12 + k], w_ih[(j+H_)*12 + k]);
        g_pIn [k*H_ + j] = w_ih[(j+2*H_)*12 + k];
    }
}

// ---------------- dynamic smem layout (float offsets) -----------------------
#define OFF_H     0        // sh_h [2][128 j][8 b]          (2048)
#define OFF_HD    2048     // sh_hd[128 j][8 b]  SINGLE     (1024)
#define OFF_GIN   3072     // sh_gin[12][8]      SINGLE     (128, 96 used)
#define OFF_HID1  3200     // sh_hid1[8 b][128 j]           (1024)
#define OFF_HIDU  4224     // sh_hidu[8 b][64 u] / upart overlay (512)
#define OFF_PART  4736     // gate exchange: 2 x 8 slots x 128 ull (4096)
#define OFF_WRZ   8832     // s_wrz [128 k][128 j] float2   (32768)
#define OFF_WN    41600    // s_wn  [128 k][128 j] float    (16384)
#define SMEM_FLOATS 57984
#define SMEM_BYTES  (SMEM_FLOATS * 4)   // 231,936 <= 232,448

__global__ void __launch_bounds__(NTHR, 1) grud_kernel(
    const float* __restrict__ x,
    const float* __restrict__ x_mean,
    const float* __restrict__ dxw, const float* __restrict__ dxb,
    const float* __restrict__ dhw, const float* __restrict__ dhb,
    const float* __restrict__ b_ih, const float* __restrict__ b_hh,
    const float* __restrict__ b1,
    const float* __restrict__ w2,  const float* __restrict__ b2,
    const float* __restrict__ bu1,
    const float* __restrict__ wu2, const float* __restrict__ bu2,
    float* __restrict__ out)
{
    extern __shared__ float smem[];
    float*  sh_hd  = smem + OFF_HD;
    float*  sh_gin = smem + OFF_GIN;
    float*  sh_hid1= smem + OFF_HID1;
    float*  sh_hidu= smem + OFF_HIDU;
    ull*    s_up   = (ull*)(smem + OFF_HIDU);     // overlay (sequenced by BARH)
    ull*    s_part = (ull*)(smem + OFF_PART);
    float2* s_wrz  = (float2*)(smem + OFF_WRZ);
    float*  s_wn   = smem + OFF_WN;

    const int tid = threadIdx.x;
    const int b0  = blockIdx.x * BPC;
    const bool isGate = (tid < 256);

    // ---- stage gate weight planes into shared (once) ------------------------
    for (int i = tid; i < H_*H_; i += NTHR) { s_wrz[i] = g_wrz[i]; s_wn[i] = g_wn[i]; }
    for (int i = tid; i < 1024; i += NTHR) { smem[OFF_H + i] = 0.f; sh_hd[i] = 0.f; }

    // ======================= per-role constants ==============================
    const int half = (tid >> 7) & 1;      // gate half
    const int j    = tid & 127;
    const int hj    = tid - 256;          // head index
    const int u     = hj & 63;
    const int khalf = hj >> 6;            // warp-uniform in head group

    float bihr=0,bihz=0,bihn=0,bhhr=0,bhhz=0,bhhn=0,dhwj=0,dhbj=0;
    if (isGate) {
        bihr=b_ih[j]; bihz=b_ih[H_+j]; bihn=b_ih[2*H_+j];
        bhhr=b_hh[j]; bhhz=b_hh[H_+j]; bhhn=b_hh[2*H_+j];
        dhwj=dhw[j];  dhbj=dhb[j];
    }
    float b1h=0, bu1u=0;
    if (!isGate) { b1h = b1[hj]; bu1u = bu1[u]; }

    // phase-A constants: tid<48 -> (batch ab, feature ac)
    const int ab = tid / 6, ac = tid - ab * 6;
    float xm=0, axw=0, axb=0;
    if (tid < 48) { xm = x_mean[ac]; axw = dxw[ac]; axb = dxb[ac]; }
    // head reducers
    const int pb = hj / 6, pc = hj - pb * 6;          // pred: hj<48
    const int vi = hj - 64;
    const int ub = vi / 6, uc = vi - ub * 6;          // unc: 0<=vi<48
    float b2c=0, bu2c=0;
    if (!isGate && hj < 48) b2c = b2[pc];
    if (!isGate && vi >= 0 && vi < 48) bu2c = bu2[uc];

    const float* xpA = x + (size_t)(b0 + ab) * T_ * 13;             // phase A
    const float* pD  = x + (size_t)(b0 + half*4) * T_ * 13 + 12;    // dt base
    const size_t DST = (size_t)T_ * 13;

    float running = 0.f, xlast = 0.f;
    float hdecP[4] = {0.f, 0.f, 0.f, 0.f};

    // ---- pre-loop: phase A for t=0 into gin ---------------------------------
    if (tid < 48) {
        float xv = xpA[ac], mm = xpA[6+ac], dtv = xpA[12];
        bool obs = (mm > 0.5f);
        running = obs ? 0.f : (running + dtv);
        float gx = __expf(-fmaxf(running * axw + axb, 0.f));
        xlast = obs ? xv : xlast;
        float xhat = mm*xv + (1.f-mm)*(gx*xlast + (1.f-gx)*xm);
        sh_gin[ac*8 + ab]     = xhat;
        sh_gin[(6+ac)*8 + ab] = mm;
    }

    const int kg0 = half * 64;
    const float2* wrzp = s_wrz + (size_t)kg0*H_ + j;
    const float*  wnp  = s_wn  + (size_t)kg0*H_ + j;

    for (int t = 0; t <= T_; ++t) {
        __syncthreads();
        const int c = t & 1, nb = c ^ 1;
        const float* sh_hc = smem + OFF_H + c*1024;

        if (isGate) {
            if (t < T_) {
                // ---- prefetch t+1 inputs + w_ih rows (regs) -----------------
                float xv_n=0, mm_n=0, dtv_n=0;
                float dtn[4] = {0.f,0.f,0.f,0.f};
                if (t + 1 < T_) {
                    if (tid < 48) {
                        const float* xp = xpA + (size_t)(t+1)*13;
                        xv_n = xp[ac]; mm_n = xp[6+ac]; dtv_n = xp[12];
                    }
                    const float* pdt = pD + (size_t)(t+1)*13;
                    #pragma unroll
                    for (int lb = 0; lb < 4; lb++) dtn[lb] = pdt[lb*DST];
                }
                float2 wiRZ[6]; float wiN[6];
                {
                    int kin0 = half * 6;
                    #pragma unroll
                    for (int kk = 0; kk < 6; kk++) {
                        wiRZ[kk] = __ldg(g_pIrz + (kin0+kk)*H_ + j);
                        wiN[kk]  = __ldg(g_pIn  + (kin0+kk)*H_ + j);
                    }
                }

                // ---- gate GEMV: 64 all-smem rows ----------------------------
                ull aR[4], aZ[4], aGN[4], aIN[4];
                #pragma unroll
                for (int p = 0; p < 4; p++) { aR[p]=0; aZ[p]=0; aGN[p]=0; aIN[p]=0; }

                #pragma unroll 4
                for (int i = 0; i < 64; i++) {
                    float2 wrz = wrzp[(size_t)i*H_];
                    float  wnv = wnp[(size_t)i*H_];
                    int k = kg0 + i;
                    ulonglong2 dA = *(const ulonglong2*)(sh_hd + k*8);
                    ulonglong2 dB = *(const ulonglong2*)(sh_hd + k*8 + 4);
                    ull wr = pk2(wrz.x,wrz.x), wz = pk2(wrz.y,wrz.y), wn_ = pk2(wnv,wnv);
                    fma2(aR[0],dA.x,wr);  fma2(aR[1],dA.y,wr);  fma2(aR[2],dB.x,wr);  fma2(aR[3],dB.y,wr);
                    fma2(aZ[0],dA.x,wz);  fma2(aZ[1],dA.y,wz);  fma2(aZ[2],dB.x,wz);  fma2(aZ[3],dB.y,wz);
                    fma2(aGN[0],dA.x,wn_);fma2(aGN[1],dA.y,wn_);fma2(aGN[2],dB.x,wn_);fma2(aGN[3],dB.y,wn_);
                }
                // input-to-hidden rows (prefetched weights, gin broadcasts)
                {
                    int kin0 = half * 6;
                    #pragma unroll
                    for (int kk = 0; kk < 6; kk++) {
                        int k = kin0 + kk;
                        ull wr = pk2(wiRZ[kk].x,wiRZ[kk].x), wz = pk2(wiRZ[kk].y,wiRZ[kk].y);
                        ull wn_ = pk2(wiN[kk],wiN[kk]);
                        ulonglong2 gA = *(const ulonglong2*)(sh_gin + k*8);
                        ulonglong2 gB = *(const ulonglong2*)(sh_gin + k*8 + 4);
                        fma2(aR[0],gA.x,wr); fma2(aR[1],gA.y,wr); fma2(aR[2],gB.x,wr); fma2(aR[3],gB.y,wr);
                        fma2(aZ[0],gA.x,wz); fma2(aZ[1],gA.y,wz); fma2(aZ[2],gB.x,wz); fma2(aZ[3],gB.y,wz);
                        fma2(aIN[0],gA.x,wn_);fma2(aIN[1],gA.y,wn_);fma2(aIN[2],gB.x,wn_);fma2(aIN[3],gB.y,wn_);
                    }
                }

                // ---- exchange partials (gate-only barrier) ------------------
                {
                    int fp = (1 - half) * 2;
                    ull* ws = s_part + (size_t)(half*8)*128 + j;
                    ws[0*128] = aR[fp];  ws[1*128] = aR[fp+1];
                    ws[2*128] = aZ[fp];  ws[3*128] = aZ[fp+1];
                    ws[4*128] = aGN[fp]; ws[5*128] = aGN[fp+1];
                    ws[6*128] = aIN[fp]; ws[7*128] = aIN[fp+1];
                }
                BARG();
                const int op = half * 2;
                {
                    const ull* rs = s_part + (size_t)((1-half)*8)*128 + j;
                    add2(aR[op],  rs[0*128]); add2(aR[op+1],  rs[1*128]);
                    add2(aZ[op],  rs[2*128]); add2(aZ[op+1],  rs[3*128]);
                    add2(aGN[op], rs[4*128]); add2(aGN[op+1], rs[5*128]);
                    add2(aIN[op], rs[6*128]); add2(aIN[op+1], rs[7*128]);
                }

                // ---- gates + h update + next decay --------------------------
                float fR[4], fZ[4], fGN[4], fIN[4];
                float2 v;
                v = up2(aR[op]);    fR[0]=v.x;  fR[1]=v.y;
                v = up2(aR[op+1]);  fR[2]=v.x;  fR[3]=v.y;
                v = up2(aZ[op]);    fZ[0]=v.x;  fZ[1]=v.y;
                v = up2(aZ[op+1]);  fZ[2]=v.x;  fZ[3]=v.y;
                v = up2(aGN[op]);   fGN[0]=v.x; fGN[1]=v.y;
                v = up2(aGN[op+1]); fGN[2]=v.x; fGN[3]=v.y;
                v = up2(aIN[op]);   fIN[0]=v.x; fIN[1]=v.y;
                v = up2(aIN[op+1]); fIN[2]=v.x; fIN[3]=v.y;

                float hNew[4], hdN[4];
                #pragma unroll
                for (int lb = 0; lb < 4; lb++) {
                    float r = sigf(fR[lb] + bihr + bhhr);
                    float z = sigf(fZ[lb] + bihz + bhhz);
                    float n = tanhfast(fIN[lb] + bihn + r * (fGN[lb] + bhhn));
                    hNew[lb] = n + z * (hdecP[lb] - n);
                    float g = __expf(-fmaxf(dtn[lb] * dhwj + dhbj, 0.f));
                    hdN[lb] = hNew[lb] * g;
                    hdecP[lb] = hdN[lb];
                }
                // safe post-BARG: all gate GEMV reads of hd/gin are complete
                *(float4*)(smem + OFF_H + nb*1024 + j*8 + half*4) = make_float4(hNew[0],hNew[1],hNew[2],hNew[3]);
                *(float4*)(sh_hd + j*8 + half*4) = make_float4(hdN[0],hdN[1],hdN[2],hdN[3]);

                // ---- phase A for t+1 (post-BARG; single gin buffer) ---------
                if (t + 1 < T_ && tid < 48) {
                    bool obs = (mm_n > 0.5f);
                    running = obs ? 0.f : (running + dtv_n);
                    float gx = __expf(-fmaxf(running * axw + axb, 0.f));
                    xlast = obs ? xv_n : xlast;
                    float xhat = mm_n*xv_n + (1.f-mm_n)*(gx*xlast + (1.f-gx)*xm);
                    sh_gin[ac*8 + ab]     = xhat;
                    sh_gin[(6+ac)*8 + ab] = mm_n;
                }
            }
        } else {
            if (t >= 1) {
                // ---- head GEMV on h(t-1) = sh_hc; weights streamed from L2 --
                ull aP[4], aU[4];
                #pragma unroll
                for (int p = 0; p < 4; p++) { aP[p]=0; aU[p]=0; }

                #define PROW(KK) do {                                            \
                    float wpv = __ldg(g_w1T + (KK)*H_ + hj); ull wp = pk2(wpv, wpv); \
                    ulonglong2 hA = *(const ulonglong2*)(sh_hc + (KK)*8);        \
                    ulonglong2 hB = *(const ulonglong2*)(sh_hc + (KK)*8 + 4);    \
                    fma2(aP[0],hA.x,wp); fma2(aP[1],hA.y,wp);                    \
                    fma2(aP[2],hB.x,wp); fma2(aP[3],hB.y,wp);                    \
                } while (0)
                #define PUROW(KK) do {                                           \
                    float wpv = __ldg(g_w1T + (KK)*H_ + hj); ull wp = pk2(wpv, wpv); \
                    float wuv = __ldg(g_wu1T + (KK)*64 + u); ull wu_ = pk2(wuv, wuv); \
                    ulonglong2 hA = *(const ulonglong2*)(sh_hc + (KK)*8);        \
                    ulonglong2 hB = *(const ulonglong2*)(sh_hc + (KK)*8 + 4);    \
                    fma2(aP[0],hA.x,wp);  fma2(aP[1],hA.y,wp);                   \
                    fma2(aP[2],hB.x,wp);  fma2(aP[3],hB.y,wp);                   \
                    fma2(aU[0],hA.x,wu_); fma2(aU[1],hA.y,wu_);                  \
                    fma2(aU[2],hB.x,wu_); fma2(aU[3],hB.y,wu_);                  \
                } while (0)

                if (khalf == 0) {   // U over k in [0,64)
                    #pragma unroll 8
                    for (int k = 0; k < 64; k++)   PUROW(k);
                    #pragma unroll 8
                    for (int k = 64; k < 128; k++) PROW(k);
                } else {            // U over k in [64,128)
                    #pragma unroll 8
                    for (int k = 0; k < 64; k++)   PROW(k);
                    #pragma unroll 8
                    for (int k = 64; k < 128; k++) PUROW(k);
                }
                #undef PROW
                #undef PUROW

                // hid1 = relu(P + b1): 8 batches for this hj
                {
                    float2 v;
                    #pragma unroll
                    for (int p = 0; p < 4; p++) {
                        v = up2(aP[p]);
                        sh_hid1[(2*p  )*H_ + hj] = fmaxf(v.x + b1h, 0.f);
                        sh_hid1[(2*p+1)*H_ + hj] = fmaxf(v.y + b1h, 0.f);
                    }
                }
                // U partials (khalf1 -> overlay region)
                if (khalf == 1) {
                    #pragma unroll
                    for (int p = 0; p < 4; p++) s_up[p*64 + u] = aU[p];
                }
                BARH();   // hid1 + upart visible
                ull uin[4];
                if (khalf == 0) {
                    #pragma unroll
                    for (int p = 0; p < 4; p++) uin[p] = s_up[p*64 + u];
                }
                BARH();   // upart reads complete before hidu overwrites region
                if (khalf == 0) {
                    float2 v;
                    #pragma unroll
                    for (int p = 0; p < 4; p++) {
                        add2(aU[p], uin[p]);
                        v = up2(aU[p]);
                        sh_hidu[(2*p  )*64 + u] = fmaxf(v.x + bu1u, 0.f);
                        sh_hidu[(2*p+1)*64 + u] = fmaxf(v.y + bu1u, 0.f);
                    }
                }
                // pred reduction (hid1 stable since first BARH)
                if (hj < 48) {
                    float acc = b2c;
                    const float* wrow = w2 + pc * H_;
                    const float* hrow = sh_hid1 + pb * H_;
                    #pragma unroll 4
                    for (int k = 0; k < H_; k += 4) {
                        float4 hh = *(const float4*)(hrow + k);
                        float4 ww = *(const float4*)(wrow + k);
                        acc += hh.x*ww.x + hh.y*ww.y + hh.z*ww.z + hh.w*ww.w;
                    }
                    out[((size_t)(b0 + pb) * T_ + (t - 1)) * C_ + pc] = acc;
                }
                BARH();   // hidu ready
                if (vi >= 0 && vi < 48) {
                    float acc = bu2c;
                    const float* wrow = wu2 + uc * 64;
                    const float* hrow = sh_hidu + ub * 64;
                    #pragma unroll 4
                    for (int k = 0; k < 64; k += 4) {
                        float4 hh = *(const float4*)(hrow + k);
                        float4 ww = *(const float4*)(wrow + k);
                        acc += hh.x*ww.x + hh.y*ww.y + hh.z*ww.z + hh.w*ww.w;
                    }
                    float sp = fmaxf(acc, 0.f) + log1pf(__expf(-fabsf(acc)));
                    out[(size_t)B_*T_*C_ + ((size_t)(b0 + ub) * T_ + (t - 1)) * C_ + uc] = sp;
                }
            }
        }
    }
}

extern "C" void kernel_launch(void* const* d_in, const int* in_sizes, int n_in,
                              void* d_out, int out_size) {
    const float* x      = (const float*)d_in[0];
    const float* x_mean = (const float*)d_in[1];
    const float* dxw    = (const float*)d_in[2];
    const float* dxb    = (const float*)d_in[3];
    const float* dhw    = (const float*)d_in[4];
    const float* dhb    = (const float*)d_in[5];
    const float* w_ih   = (const float*)d_in[6];
    const float* w_hh   = (const float*)d_in[7];
    const float* b_ih   = (const float*)d_in[8];
    const float* b_hh   = (const float*)d_in[9];
    const float* w1     = (const float*)d_in[10];
    const float* b1     = (const float*)d_in[11];
    const float* w2     = (const float*)d_in[12];
    const float* b2     = (const float*)d_in[13];
    const float* wu1    = (const float*)d_in[14];
    const float* bu1    = (const float*)d_in[15];
    const float* wu2    = (const float*)d_in[16];
    const float* bu2    = (const float*)d_in[17];
    float* out = (float*)d_out;

    // idempotent, not stream-captured; no static guards
    cudaFuncSetAttribute(grud_kernel, cudaFuncAttributeMaxDynamicSharedMemorySize, SMEM_BYTES);

    pack_kernel<<<NCTA, 128>>>(w_ih, w_hh, w1, wu1);
    grud_kernel<<<NCTA, NTHR, SMEM_BYTES>>>(x, x_mean, dxw, dxb, dhw, dhb,
                                            b_ih, b_hh, b1, w2, b2, bu1, wu2, bu2, out);
}

// round 14
// speedup vs baseline: 1.0662x; 1.0662x over previous
#include <cuda_runtime.h>
#include <cstdint>

typedef unsigned long long ull;

#define B_   1024
#define T_   1024
#define H_   128
#define C_   6
#define BPC  8
#define NCTA (B_/BPC)     // 128
#define NTHR 384          // 8 gate warps (256) + 4 head warps (128)

// ---------------- packed transposed weights (device globals) ---------------
__device__ float2 g_wrz[H_*H_];    // [k][j] = (whh_r[j][k], whh_z[j][k])
__device__ float  g_wn [H_*H_];    // [k][j] = whh_n[j][k]
__device__ float  g_w1T[H_*H_];    // [k][j] = w1[j][k]      (head stream)
__device__ float  g_wu1T[H_*64];   // [k][u] = wu1[u][k]     (head stream)
__device__ float2 g_pIrz[12*H_];   // [k][j] = (wih_r, wih_z)[j][k]
__device__ float  g_pIn [12*H_];   // [k][j] = wih_n[j][k]

// ---------------- f32x2 helpers --------------------------------------------
__device__ __forceinline__ ull pk2(float a, float b){
    ull r; asm("mov.b64 %0, {%1,%2};" : "=l"(r) : "f"(a), "f"(b)); return r;
}
__device__ __forceinline__ void fma2(ull& d, ull a, ull b){
    asm("fma.rn.f32x2 %0, %1, %2, %3;" : "=l"(d) : "l"(a), "l"(b), "l"(d));
}
__device__ __forceinline__ void add2(ull& d, ull a){
    asm("add.rn.f32x2 %0, %1, %2;" : "=l"(d) : "l"(d), "l"(a));
}
__device__ __forceinline__ float2 up2(ull v){
    float2 r; asm("mov.b64 {%0,%1}, %2;" : "=f"(r.x), "=f"(r.y) : "l"(v)); return r;
}
__device__ __forceinline__ float sigf(float x){
    return __fdividef(1.f, 1.f + __expf(-x));
}
__device__ __forceinline__ float tanhfast(float x){
    float e = __expf(-2.f * fabsf(x));
    float t = __fdividef(1.f - e, 1.f + e);
    return copysignf(t, x);
}
// gate-internal / head-internal barriers
#define BARG() asm volatile("bar.sync 1, 256;" ::: "memory")
#define BARH() asm volatile("bar.sync 2, 128;" ::: "memory")
// producer-consumer ring barriers (count = 384 = all threads)
#define BAR_SYNC(id)   asm volatile("bar.sync %0, 384;"   :: "r"(id) : "memory")
#define BAR_ARRIVE(id) asm volatile("bar.arrive %0, 384;" :: "r"(id) : "memory")
#define FULL0  3
#define EMPTY0 5

// ---------------- weight pack pre-pass -------------------------------------
__global__ void pack_kernel(const float* __restrict__ w_ih, const float* __restrict__ w_hh,
                            const float* __restrict__ w1,   const float* __restrict__ wu1){
    int idx = blockIdx.x * blockDim.x + threadIdx.x;   // 0..16383
    int k = idx >> 7, j = idx & 127;
    g_wrz[idx] = make_float2(w_hh[j*H_ + k], w_hh[(j+H_)*H_ + k]);
    g_wn[idx]  = w_hh[(j+2*H_)*H_ + k];
    g_w1T[idx] = w1[j*H_ + k];
    if (j < 64)  g_wu1T[k*64 + j] = wu1[j*H_ + k];
    if (k < 12) {
        g_pIrz[k*H_ + j] = make_float2(w_ih[j*12 + k], w_ih[(j+H_)*12 + k]);
        g_pIn [k*H_ + j] = w_ih[(j+2*H_)*12 + k];
    }
}

// ---------------- dynamic smem layout (float offsets) -----------------------
#define OFF_H     0        // sh_h [2][128 j][8 b]  ring     (2048)
#define OFF_HD    2048     // sh_hd[128 j][8 b]  gate-priv   (1024)
#define OFF_GIN   3072     // sh_gin[12][8]      gate-priv   (128)
#define OFF_HID1  3200     // sh_hid1[8 b][128 j] head-priv  (1024)
#define OFF_HIDU  4224     // sh_hidu / upart overlay        (512)
#define OFF_PART  4736     // gate exchange                  (4096)
#define OFF_WRZ   8832     // s_wrz [128 k][128 j] float2    (32768)
#define OFF_WN    41600    // s_wn  [128 k][128 j] float     (16384)
#define SMEM_FLOATS 57984
#define SMEM_BYTES  (SMEM_FLOATS * 4)   // 231,936 <= 232,448

__global__ void __launch_bounds__(NTHR, 1) grud_kernel(
    const float* __restrict__ x,
    const float* __restrict__ x_mean,
    const float* __restrict__ dxw, const float* __restrict__ dxb,
    const float* __restrict__ dhw, const float* __restrict__ dhb,
    const float* __restrict__ b_ih, const float* __restrict__ b_hh,
    const float* __restrict__ b1,
    const float* __restrict__ w2,  const float* __restrict__ b2,
    const float* __restrict__ bu1,
    const float* __restrict__ wu2, const float* __restrict__ bu2,
    float* __restrict__ out)
{
    extern __shared__ float smem[];
    float*  sh_hd  = smem + OFF_HD;
    float*  sh_gin = smem + OFF_GIN;
    float*  sh_hid1= smem + OFF_HID1;
    float*  sh_hidu= smem + OFF_HIDU;
    ull*    s_up   = (ull*)(smem + OFF_HIDU);
    ull*    s_part = (ull*)(smem + OFF_PART);
    float2* s_wrz  = (float2*)(smem + OFF_WRZ);
    float*  s_wn   = smem + OFF_WN;

    const int tid = threadIdx.x;
    const int b0  = blockIdx.x * BPC;
    const bool isGate = (tid < 256);

    // ---- stage weights into shared (once) ----------------------------------
    for (int i = tid; i < H_*H_; i += NTHR) { s_wrz[i] = g_wrz[i]; s_wn[i] = g_wn[i]; }
    for (int i = tid; i < 1024; i += NTHR) sh_hd[i] = 0.f;

    const int half = (tid >> 7) & 1;
    const int j    = tid & 127;
    const int hj    = tid - 256;
    const int u     = hj & 63;
    const int khalf = hj >> 6;

    float bihr=0,bihz=0,bihn=0,bhhr=0,bhhz=0,bhhn=0,dhwj=0,dhbj=0;
    if (isGate) {
        bihr=b_ih[j]; bihz=b_ih[H_+j]; bihn=b_ih[2*H_+j];
        bhhr=b_hh[j]; bhhz=b_hh[H_+j]; bhhn=b_hh[2*H_+j];
        dhwj=dhw[j];  dhbj=dhb[j];
    }
    float b1h=0, bu1u=0;
    if (!isGate) { b1h = b1[hj]; bu1u = bu1[u]; }

    const int ab = tid / 6, ac = tid - ab * 6;
    float xm=0, axw=0, axb=0;
    if (tid < 48) { xm = x_mean[ac]; axw = dxw[ac]; axb = dxb[ac]; }
    const int pb = hj / 6, pc = hj - pb * 6;
    const int vi = hj - 64;
    const int ub = vi / 6, uc = vi - ub * 6;
    float b2c=0, bu2c=0;
    if (!isGate && hj < 48) b2c = b2[pc];
    if (!isGate && vi >= 0 && vi < 48) bu2c = bu2[uc];

    const float* xpA = x + (size_t)(b0 + ab) * T_ * 13;
    const float* pD  = x + (size_t)(b0 + half*4) * T_ * 13 + 12;
    const size_t DST = (size_t)T_ * 13;

    float running = 0.f, xlast = 0.f;
    float hdecP[4] = {0.f, 0.f, 0.f, 0.f};

    // pre-loop: phase A for t=0 (gate threads)
    if (tid < 48) {
        float xv = xpA[ac], mm = xpA[6+ac], dtv = xpA[12];
        bool obs = (mm > 0.5f);
        running = obs ? 0.f : (running + dtv);
        float gx = __expf(-fmaxf(running * axw + axb, 0.f));
        xlast = obs ? xv : xlast;
        float xhat = mm*xv + (1.f-mm)*(gx*xlast + (1.f-gx)*xm);
        sh_gin[ac*8 + ab]     = xhat;
        sh_gin[(6+ac)*8 + ab] = mm;
    }
    __syncthreads();   // staging + gin(0) visible

    if (isGate) {
        // ================= GATE GROUP: recurrent producer ===================
        const int kg0 = half * 64;
        const float2* wrzp = s_wrz + (size_t)kg0*H_ + j;
        const float*  wnp  = s_wn  + (size_t)kg0*H_ + j;

        for (int t = 0; t < T_; ++t) {
            const int s = t & 1;
            // prefetch t+1 inputs + w_ih rows
            float xv_n=0, mm_n=0, dtv_n=0;
            float dtn[4] = {0.f,0.f,0.f,0.f};
            if (t + 1 < T_) {
                if (tid < 48) {
                    const float* xp = xpA + (size_t)(t+1)*13;
                    xv_n = xp[ac]; mm_n = xp[6+ac]; dtv_n = xp[12];
                }
                const float* pdt = pD + (size_t)(t+1)*13;
                #pragma unroll
                for (int lb = 0; lb < 4; lb++) dtn[lb] = pdt[lb*DST];
            }
            float2 wiRZ[6]; float wiN[6];
            {
                int kin0 = half * 6;
                #pragma unroll
                for (int kk = 0; kk < 6; kk++) {
                    wiRZ[kk] = __ldg(g_pIrz + (kin0+kk)*H_ + j);
                    wiN[kk]  = __ldg(g_pIn  + (kin0+kk)*H_ + j);
                }
            }

            // gate GEMV: 64 all-smem rows
            ull aR[4], aZ[4], aGN[4], aIN[4];
            #pragma unroll
            for (int p = 0; p < 4; p++) { aR[p]=0; aZ[p]=0; aGN[p]=0; aIN[p]=0; }

            #pragma unroll 4
            for (int i = 0; i < 64; i++) {
                float2 wrz = wrzp[(size_t)i*H_];
                float  wnv = wnp[(size_t)i*H_];
                int k = kg0 + i;
                ulonglong2 dA = *(const ulonglong2*)(sh_hd + k*8);
                ulonglong2 dB = *(const ulonglong2*)(sh_hd + k*8 + 4);
                ull wr = pk2(wrz.x,wrz.x), wz = pk2(wrz.y,wrz.y), wn_ = pk2(wnv,wnv);
                fma2(aR[0],dA.x,wr);  fma2(aR[1],dA.y,wr);  fma2(aR[2],dB.x,wr);  fma2(aR[3],dB.y,wr);
                fma2(aZ[0],dA.x,wz);  fma2(aZ[1],dA.y,wz);  fma2(aZ[2],dB.x,wz);  fma2(aZ[3],dB.y,wz);
                fma2(aGN[0],dA.x,wn_);fma2(aGN[1],dA.y,wn_);fma2(aGN[2],dB.x,wn_);fma2(aGN[3],dB.y,wn_);
            }
            {
                int kin0 = half * 6;
                #pragma unroll
                for (int kk = 0; kk < 6; kk++) {
                    int k = kin0 + kk;
                    ull wr = pk2(wiRZ[kk].x,wiRZ[kk].x), wz = pk2(wiRZ[kk].y,wiRZ[kk].y);
                    ull wn_ = pk2(wiN[kk],wiN[kk]);
                    ulonglong2 gA = *(const ulonglong2*)(sh_gin + k*8);
                    ulonglong2 gB = *(const ulonglong2*)(sh_gin + k*8 + 4);
                    fma2(aR[0],gA.x,wr); fma2(aR[1],gA.y,wr); fma2(aR[2],gB.x,wr); fma2(aR[3],gB.y,wr);
                    fma2(aZ[0],gA.x,wz); fma2(aZ[1],gA.y,wz); fma2(aZ[2],gB.x,wz); fma2(aZ[3],gB.y,wz);
                    fma2(aIN[0],gA.x,wn_);fma2(aIN[1],gA.y,wn_);fma2(aIN[2],gB.x,wn_);fma2(aIN[3],gB.y,wn_);
                }
            }

            // exchange partials (gate-only)
            {
                int fp = (1 - half) * 2;
                ull* ws = s_part + (size_t)(half*8)*128 + j;
                ws[0*128] = aR[fp];  ws[1*128] = aR[fp+1];
                ws[2*128] = aZ[fp];  ws[3*128] = aZ[fp+1];
                ws[4*128] = aGN[fp]; ws[5*128] = aGN[fp+1];
                ws[6*128] = aIN[fp]; ws[7*128] = aIN[fp+1];
            }
            BARG();
            const int op = half * 2;
            {
                const ull* rs = s_part + (size_t)((1-half)*8)*128 + j;
                add2(aR[op],  rs[0*128]); add2(aR[op+1],  rs[1*128]);
                add2(aZ[op],  rs[2*128]); add2(aZ[op+1],  rs[3*128]);
                add2(aGN[op], rs[4*128]); add2(aGN[op+1], rs[5*128]);
                add2(aIN[op], rs[6*128]); add2(aIN[op+1], rs[7*128]);
            }

            // gates + h update + next decay
            float fR[4], fZ[4], fGN[4], fIN[4];
            float2 v;
            v = up2(aR[op]);    fR[0]=v.x;  fR[1]=v.y;
            v = up2(aR[op+1]);  fR[2]=v.x;  fR[3]=v.y;
            v = up2(aZ[op]);    fZ[0]=v.x;  fZ[1]=v.y;
            v = up2(aZ[op+1]);  fZ[2]=v.x;  fZ[3]=v.y;
            v = up2(aGN[op]);   fGN[0]=v.x; fGN[1]=v.y;
            v = up2(aGN[op+1]); fGN[2]=v.x; fGN[3]=v.y;
            v = up2(aIN[op]);   fIN[0]=v.x; fIN[1]=v.y;
            v = up2(aIN[op+1]); fIN[2]=v.x; fIN[3]=v.y;

            float hNew[4], hdN[4];
            #pragma unroll
            for (int lb = 0; lb < 4; lb++) {
                float r = sigf(fR[lb] + bihr + bhhr);
                float z = sigf(fZ[lb] + bihz + bhhz);
                float n = tanhfast(fIN[lb] + bihn + r * (fGN[lb] + bhhn));
                hNew[lb] = n + z * (hdecP[lb] - n);
                float g = __expf(-fmaxf(dtn[lb] * dhwj + dhbj, 0.f));
                hdN[lb] = hNew[lb] * g;
                hdecP[lb] = hdN[lb];
            }
            // gate-private state (ordered by BARG):
            *(float4*)(sh_hd + j*8 + half*4) = make_float4(hdN[0],hdN[1],hdN[2],hdN[3]);
            if (t + 1 < T_ && tid < 48) {
                bool obs = (mm_n > 0.5f);
                running = obs ? 0.f : (running + dtv_n);
                float gx = __expf(-fmaxf(running * axw + axb, 0.f));
                xlast = obs ? xv_n : xlast;
                float xhat = mm_n*xv_n + (1.f-mm_n)*(gx*xlast + (1.f-gx)*xm);
                sh_gin[ac*8 + ab]     = xhat;
                sh_gin[(6+ac)*8 + ab] = mm_n;
            }

            // publish h(t) into ring slot s (heads freed it at t-2)
            BAR_SYNC(EMPTY0 + s);
            *(float4*)(smem + OFF_H + s*1024 + j*8 + half*4) = make_float4(hNew[0],hNew[1],hNew[2],hNew[3]);
            asm volatile("membar.cta;" ::: "memory");
            BAR_ARRIVE(FULL0 + s);
        }
        // drain: heads still arrive EMPTY for last two slots; nobody waits.
    } else {
        // ================= HEAD GROUP: consumer =============================
        // pre-arrive both EMPTY slots so gates can fill t=0,1 immediately
        BAR_ARRIVE(EMPTY0 + 0);
        BAR_ARRIVE(EMPTY0 + 1);

        for (int tt = 0; tt < T_; ++tt) {
            const int s = tt & 1;
            BAR_SYNC(FULL0 + s);
            const float* sh_hc = smem + OFF_H + s*1024;

            ull aP[4], aU[4];
            #pragma unroll
            for (int p = 0; p < 4; p++) { aP[p]=0; aU[p]=0; }

            #define PROW(KK) do {                                            \
                float wpv = __ldg(g_w1T + (KK)*H_ + hj); ull wp = pk2(wpv, wpv); \
                ulonglong2 hA = *(const ulonglong2*)(sh_hc + (KK)*8);        \
                ulonglong2 hB = *(const ulonglong2*)(sh_hc + (KK)*8 + 4);    \
                fma2(aP[0],hA.x,wp); fma2(aP[1],hA.y,wp);                    \
                fma2(aP[2],hB.x,wp); fma2(aP[3],hB.y,wp);                    \
            } while (0)
            #define PUROW(KK) do {                                           \
                float wpv = __ldg(g_w1T + (KK)*H_ + hj); ull wp = pk2(wpv, wpv); \
                float wuv = __ldg(g_wu1T + (KK)*64 + u); ull wu_ = pk2(wuv, wuv); \
                ulonglong2 hA = *(const ulonglong2*)(sh_hc + (KK)*8);        \
                ulonglong2 hB = *(const ulonglong2*)(sh_hc + (KK)*8 + 4);    \
                fma2(aP[0],hA.x,wp);  fma2(aP[1],hA.y,wp);                   \
                fma2(aP[2],hB.x,wp);  fma2(aP[3],hB.y,wp);                   \
                fma2(aU[0],hA.x,wu_); fma2(aU[1],hA.y,wu_);                  \
                fma2(aU[2],hB.x,wu_); fma2(aU[3],hB.y,wu_);                  \
            } while (0)

            if (khalf == 0) {
                #pragma unroll 8
                for (int k = 0; k < 64; k++)   PUROW(k);
                #pragma unroll 8
                for (int k = 64; k < 128; k++) PROW(k);
            } else {
                #pragma unroll 8
                for (int k = 0; k < 64; k++)   PROW(k);
                #pragma unroll 8
                for (int k = 64; k < 128; k++) PUROW(k);
            }
            #undef PROW
            #undef PUROW

            // done reading sh_hc (accumulators hold everything) -> free slot
            BAR_ARRIVE(EMPTY0 + s);

            // hid1 = relu(P + b1)
            {
                float2 v;
                #pragma unroll
                for (int p = 0; p < 4; p++) {
                    v = up2(aP[p]);
                    sh_hid1[(2*p  )*H_ + hj] = fmaxf(v.x + b1h, 0.f);
                    sh_hid1[(2*p+1)*H_ + hj] = fmaxf(v.y + b1h, 0.f);
                }
            }
            if (khalf == 1) {
                #pragma unroll
                for (int p = 0; p < 4; p++) s_up[p*64 + u] = aU[p];
            }
            BARH();
            ull uin[4];
            if (khalf == 0) {
                #pragma unroll
                for (int p = 0; p < 4; p++) uin[p] = s_up[p*64 + u];
            }
            BARH();
            if (khalf == 0) {
                float2 v;
                #pragma unroll
                for (int p = 0; p < 4; p++) {
                    add2(aU[p], uin[p]);
                    v = up2(aU[p]);
                    sh_hidu[(2*p  )*64 + u] = fmaxf(v.x + bu1u, 0.f);
                    sh_hidu[(2*p+1)*64 + u] = fmaxf(v.y + bu1u, 0.f);
                }
            }
            if (hj < 48) {
                float acc = b2c;
                const float* wrow = w2 + pc * H_;
                const float* hrow = sh_hid1 + pb * H_;
                #pragma unroll 4
                for (int k = 0; k < H_; k += 4) {
                    float4 hh = *(const float4*)(hrow + k);
                    float4 ww = *(const float4*)(wrow + k);
                    acc += hh.x*ww.x + hh.y*ww.y + hh.z*ww.z + hh.w*ww.w;
                }
                out[((size_t)(b0 + pb) * T_ + tt) * C_ + pc] = acc;
            }
            BARH();
            if (vi >= 0 && vi < 48) {
                float acc = bu2c;
                const float* wrow = wu2 + uc * 64;
                const float* hrow = sh_hidu + ub * 64;
                #pragma unroll 4
                for (int k = 0; k < 64; k += 4) {
                    float4 hh = *(const float4*)(hrow + k);
                    float4 ww = *(const float4*)(wrow + k);
                    acc += hh.x*ww.x + hh.y*ww.y + hh.z*ww.z + hh.w*ww.w;
                }
                float sp = fmaxf(acc, 0.f) + log1pf(__expf(-fabsf(acc)));
                out[(size_t)B_*T_*C_ + ((size_t)(b0 + ub) * T_ + tt) * C_ + uc] = sp;
            }
        }
    }
}

extern "C" void kernel_launch(void* const* d_in, const int* in_sizes, int n_in,
                              void* d_out, int out_size) {
    const float* x      = (const float*)d_in[0];
    const float* x_mean = (const float*)d_in[1];
    const float* dxw    = (const float*)d_in[2];
    const float* dxb    = (const float*)d_in[3];
    const float* dhw    = (const float*)d_in[4];
    const float* dhb    = (const float*)d_in[5];
    const float* w_ih   = (const float*)d_in[6];
    const float* w_hh   = (const float*)d_in[7];
    const float* b_ih   = (const float*)d_in[8];
    const float* b_hh   = (const float*)d_in[9];
    const float* w1     = (const float*)d_in[10];
    const float* b1     = (const float*)d_in[11];
    const float* w2     = (const float*)d_in[12];
    const float* b2     = (const float*)d_in[13];
    const float* wu1    = (const float*)d_in[14];
    const float* bu1    = (const float*)d_in[15];
    const float* wu2    = (const float*)d_in[16];
    const float* bu2    = (const float*)d_in[17];
    float* out = (float*)d_out;

    // idempotent, not stream-captured; no static guards
    cudaFuncSetAttribute(grud_kernel, cudaFuncAttributeMaxDynamicSharedMemorySize, SMEM_BYTES);

    pack_kernel<<<NCTA, 128>>>(w_ih, w_hh, w1, wu1);
    grud_kernel<<<NCTA, NTHR, SMEM_BYTES>>>(x, x_mean, dxw, dxb, dhw, dhb,
                                            b_ih, b_hh, b1, w2, b2, bu1, wu2, bu2, out);
}

// round 15
// speedup vs baseline: 1.1003x; 1.0320x over previous
#include <cuda_runtime.h>
#include <cstdint>

typedef unsigned long long ull;

#define B_   1024
#define T_   1024
#define H_   128
#define C_   6
#define BPC  8
#define NCTA (B_/BPC)     // 128
#define NTHR 384          // 8 gate warps (256) + 4 head warps (128)

// ---------------- packed transposed weights (device globals) ---------------
// pair-packed: P = k/2, o = k&1
__device__ float  g_wrz2f[64*H_*4];  // [P][j][(r0,z0,r1,z1)]
__device__ float  g_wn2f [64*H_*2];  // [P][j][(n0,n1)]
__device__ float  g_w1T2f[64*H_*2];  // [P][j][(w1_k0, w1_k1)]
__device__ float  g_wu1T2f[64*64*2]; // [P][u][(wu1_k0, wu1_k1)]
__device__ float2 g_pIrz[12*H_];     // [k][j] = (wih_r, wih_z)
__device__ float  g_pIn [12*H_];     // [k][j] = wih_n

// ---------------- f32x2 helpers --------------------------------------------
__device__ __forceinline__ ull pk2(float a, float b){
    ull r; asm("mov.b64 %0, {%1,%2};" : "=l"(r) : "f"(a), "f"(b)); return r;
}
__device__ __forceinline__ void fma2(ull& d, ull a, ull b){
    asm("fma.rn.f32x2 %0, %1, %2, %3;" : "=l"(d) : "l"(a), "l"(b), "l"(d));
}
__device__ __forceinline__ void add2(ull& d, ull a){
    asm("add.rn.f32x2 %0, %1, %2;" : "=l"(d) : "l"(d), "l"(a));
}
__device__ __forceinline__ float2 up2(ull v){
    float2 r; asm("mov.b64 {%0,%1}, %2;" : "=f"(r.x), "=f"(r.y) : "l"(v)); return r;
}
__device__ __forceinline__ float sigf(float x){
    return __fdividef(1.f, 1.f + __expf(-x));
}
__device__ __forceinline__ float tanhfast(float x){
    float e = __expf(-2.f * fabsf(x));
    float t = __fdividef(1.f - e, 1.f + e);
    return copysignf(t, x);
}
#define BARG() asm volatile("bar.sync 1, 256;" ::: "memory")
#define BARH() asm volatile("bar.sync 2, 128;" ::: "memory")
#define BAR_SYNC(id)   asm volatile("bar.sync %0, 384;"   :: "r"(id) : "memory")
#define BAR_ARRIVE(id) asm volatile("bar.arrive %0, 384;" :: "r"(id) : "memory")
#define FULL0  3
#define EMPTY0 5

// ---------------- weight pack pre-pass -------------------------------------
__global__ void pack_kernel(const float* __restrict__ w_ih, const float* __restrict__ w_hh,
                            const float* __restrict__ w1,   const float* __restrict__ wu1){
    int idx = blockIdx.x * blockDim.x + threadIdx.x;   // 0..16383
    int k = idx >> 7, j = idx & 127;
    int P = k >> 1, o = k & 1;
    g_wrz2f[P*512 + j*4 + o*2 + 0] = w_hh[j*H_ + k];         // r
    g_wrz2f[P*512 + j*4 + o*2 + 1] = w_hh[(j+H_)*H_ + k];    // z
    g_wn2f [P*256 + j*2 + o]       = w_hh[(j+2*H_)*H_ + k];  // n
    g_w1T2f[P*256 + j*2 + o]       = w1[j*H_ + k];
    if (j < 64) g_wu1T2f[P*128 + j*2 + o] = wu1[j*H_ + k];
    if (k < 12) {
        g_pIrz[k*H_ + j] = make_float2(w_ih[j*12 + k], w_ih[(j+H_)*12 + k]);
        g_pIn [k*H_ + j] = w_ih[(j+2*H_)*12 + k];
    }
}

// ---------------- dynamic smem layout (float offsets) -----------------------
#define OFF_H     0        // sh_h [2][128 j][8 b]  ring     (2048)
#define OFF_HD    2048     // sh_hd[128 j][8 b]  gate-priv   (1024)
#define OFF_GIN   3072     // sh_gin[12][8]      gate-priv   (128)
#define OFF_HID1  3200     // sh_hid1[8 b][128 j] head-priv  (1024)
#define OFF_HIDU  4224     // sh_hidu / upart overlay        (512)
#define OFF_PART  4736     // gate exchange                  (4096)
#define OFF_WRZ   8832     // s_wrz2 [64 P][128 j] float4    (32768)
#define OFF_WN    41600    // s_wn2  [64 P][128 j] float2    (16384)
#define SMEM_FLOATS 57984
#define SMEM_BYTES  (SMEM_FLOATS * 4)   // 231,936 <= 232,448

__global__ void __launch_bounds__(NTHR, 1) grud_kernel(
    const float* __restrict__ x,
    const float* __restrict__ x_mean,
    const float* __restrict__ dxw, const float* __restrict__ dxb,
    const float* __restrict__ dhw, const float* __restrict__ dhb,
    const float* __restrict__ b_ih, const float* __restrict__ b_hh,
    const float* __restrict__ b1,
    const float* __restrict__ w2,  const float* __restrict__ b2,
    const float* __restrict__ bu1,
    const float* __restrict__ wu2, const float* __restrict__ bu2,
    float* __restrict__ out)
{
    extern __shared__ float smem[];
    float*  sh_hd  = smem + OFF_HD;
    float*  sh_gin = smem + OFF_GIN;
    float*  sh_hid1= smem + OFF_HID1;
    float*  sh_hidu= smem + OFF_HIDU;
    ull*    s_up   = (ull*)(smem + OFF_HIDU);
    ull*    s_part = (ull*)(smem + OFF_PART);

    const int tid = threadIdx.x;
    const int b0  = blockIdx.x * BPC;
    const bool isGate = (tid < 256);

    // ---- stage pair-packed gate weights into shared ------------------------
    for (int i = tid; i < 64*H_*4; i += NTHR) smem[OFF_WRZ + i] = g_wrz2f[i];
    for (int i = tid; i < 64*H_*2; i += NTHR) smem[OFF_WN  + i] = g_wn2f[i];
    for (int i = tid; i < 1024; i += NTHR) sh_hd[i] = 0.f;

    const int half = (tid >> 7) & 1;
    const int j    = tid & 127;
    const int hj    = tid - 256;
    const int u     = hj & 63;
    const int khalf = hj >> 6;

    float bihr=0,bihz=0,bihn=0,bhhr=0,bhhz=0,bhhn=0,dhwj=0,dhbj=0;
    if (isGate) {
        bihr=b_ih[j]; bihz=b_ih[H_+j]; bihn=b_ih[2*H_+j];
        bhhr=b_hh[j]; bhhz=b_hh[H_+j]; bhhn=b_hh[2*H_+j];
        dhwj=dhw[j];  dhbj=dhb[j];
    }
    float b1h=0, bu1u=0;
    if (!isGate) { b1h = b1[hj]; bu1u = bu1[u]; }

    const int ab = tid / 6, ac = tid - ab * 6;
    float xm=0, axw=0, axb=0;
    if (tid < 48) { xm = x_mean[ac]; axw = dxw[ac]; axb = dxb[ac]; }
    const int pb = hj / 6, pc = hj - pb * 6;
    const int vi = hj - 64;
    const int ub = vi / 6, uc = vi - ub * 6;
    float b2c=0, bu2c=0;
    if (!isGate && hj < 48) b2c = b2[pc];
    if (!isGate && vi >= 0 && vi < 48) bu2c = bu2[uc];

    const float* xpA = x + (size_t)(b0 + ab) * T_ * 13;
    const float* pD  = x + (size_t)(b0 + half*4) * T_ * 13 + 12;
    const size_t DST = (size_t)T_ * 13;

    float running = 0.f, xlast = 0.f;
    float hdecP[4] = {0.f, 0.f, 0.f, 0.f};

    // pre-loop: phase A for t=0 (gate threads)
    if (tid < 48) {
        float xv = xpA[ac], mm = xpA[6+ac], dtv = xpA[12];
        bool obs = (mm > 0.5f);
        running = obs ? 0.f : (running + dtv);
        float gx = __expf(-fmaxf(running * axw + axb, 0.f));
        xlast = obs ? xv : xlast;
        float xhat = mm*xv + (1.f-mm)*(gx*xlast + (1.f-gx)*xm);
        sh_gin[ac*8 + ab]     = xhat;
        sh_gin[(6+ac)*8 + ab] = mm;
    }
    __syncthreads();

    if (isGate) {
        // ================= GATE GROUP: recurrent producer ===================
        const int kg0 = half * 64;                      // k base
        const float4* wrz2p = (const float4*)(smem + OFF_WRZ) + (size_t)(half*32)*H_ + j;
        const float2* wn2p  = (const float2*)(smem + OFF_WN)  + (size_t)(half*32)*H_ + j;

        for (int t = 0; t < T_; ++t) {
            const int s = t & 1;
            float xv_n=0, mm_n=0, dtv_n=0;
            float dtn[4] = {0.f,0.f,0.f,0.f};
            if (t + 1 < T_) {
                if (tid < 48) {
                    const float* xp = xpA + (size_t)(t+1)*13;
                    xv_n = xp[ac]; mm_n = xp[6+ac]; dtv_n = xp[12];
                }
                const float* pdt = pD + (size_t)(t+1)*13;
                #pragma unroll
                for (int lb = 0; lb < 4; lb++) dtn[lb] = pdt[lb*DST];
            }
            float2 wiRZ[6]; float wiN[6];
            {
                int kin0 = half * 6;
                #pragma unroll
                for (int kk = 0; kk < 6; kk++) {
                    wiRZ[kk] = __ldg(g_pIrz + (kin0+kk)*H_ + j);
                    wiN[kk]  = __ldg(g_pIn  + (kin0+kk)*H_ + j);
                }
            }

            // gate GEMV: 32 pairs (64 rows), all-smem, pair-packed weights
            ull aR[4], aZ[4], aGN[4], aIN[4];
            #pragma unroll
            for (int p = 0; p < 4; p++) { aR[p]=0; aZ[p]=0; aGN[p]=0; aIN[p]=0; }

            #pragma unroll 4
            for (int p = 0; p < 32; p++) {
                float4 wq = wrz2p[(size_t)p*H_];     // r0,z0,r1,z1
                float2 wn2 = wn2p[(size_t)p*H_];     // n0,n1
                int k = kg0 + 2*p;
                ulonglong2 dA0 = *(const ulonglong2*)(sh_hd + k*8);
                ulonglong2 dB0 = *(const ulonglong2*)(sh_hd + k*8 + 4);
                ulonglong2 dA1 = *(const ulonglong2*)(sh_hd + k*8 + 8);
                ulonglong2 dB1 = *(const ulonglong2*)(sh_hd + k*8 + 12);
                ull wr0 = pk2(wq.x,wq.x), wz0 = pk2(wq.y,wq.y), wn0 = pk2(wn2.x,wn2.x);
                fma2(aR[0],dA0.x,wr0);  fma2(aR[1],dA0.y,wr0);  fma2(aR[2],dB0.x,wr0);  fma2(aR[3],dB0.y,wr0);
                fma2(aZ[0],dA0.x,wz0);  fma2(aZ[1],dA0.y,wz0);  fma2(aZ[2],dB0.x,wz0);  fma2(aZ[3],dB0.y,wz0);
                fma2(aGN[0],dA0.x,wn0); fma2(aGN[1],dA0.y,wn0); fma2(aGN[2],dB0.x,wn0); fma2(aGN[3],dB0.y,wn0);
                ull wr1 = pk2(wq.z,wq.z), wz1 = pk2(wq.w,wq.w), wn1 = pk2(wn2.y,wn2.y);
                fma2(aR[0],dA1.x,wr1);  fma2(aR[1],dA1.y,wr1);  fma2(aR[2],dB1.x,wr1);  fma2(aR[3],dB1.y,wr1);
                fma2(aZ[0],dA1.x,wz1);  fma2(aZ[1],dA1.y,wz1);  fma2(aZ[2],dB1.x,wz1);  fma2(aZ[3],dB1.y,wz1);
                fma2(aGN[0],dA1.x,wn1); fma2(aGN[1],dA1.y,wn1); fma2(aGN[2],dB1.x,wn1); fma2(aGN[3],dB1.y,wn1);
            }
            {
                int kin0 = half * 6;
                #pragma unroll
                for (int kk = 0; kk < 6; kk++) {
                    int k = kin0 + kk;
                    ull wr = pk2(wiRZ[kk].x,wiRZ[kk].x), wz = pk2(wiRZ[kk].y,wiRZ[kk].y);
                    ull wn_ = pk2(wiN[kk],wiN[kk]);
                    ulonglong2 gA = *(const ulonglong2*)(sh_gin + k*8);
                    ulonglong2 gB = *(const ulonglong2*)(sh_gin + k*8 + 4);
                    fma2(aR[0],gA.x,wr); fma2(aR[1],gA.y,wr); fma2(aR[2],gB.x,wr); fma2(aR[3],gB.y,wr);
                    fma2(aZ[0],gA.x,wz); fma2(aZ[1],gA.y,wz); fma2(aZ[2],gB.x,wz); fma2(aZ[3],gB.y,wz);
                    fma2(aIN[0],gA.x,wn_);fma2(aIN[1],gA.y,wn_);fma2(aIN[2],gB.x,wn_);fma2(aIN[3],gB.y,wn_);
                }
            }

            // exchange partials (gate-only)
            {
                int fp = (1 - half) * 2;
                ull* ws = s_part + (size_t)(half*8)*128 + j;
                ws[0*128] = aR[fp];  ws[1*128] = aR[fp+1];
                ws[2*128] = aZ[fp];  ws[3*128] = aZ[fp+1];
                ws[4*128] = aGN[fp]; ws[5*128] = aGN[fp+1];
                ws[6*128] = aIN[fp]; ws[7*128] = aIN[fp+1];
            }
            BARG();
            const int op = half * 2;
            {
                const ull* rs = s_part + (size_t)((1-half)*8)*128 + j;
                add2(aR[op],  rs[0*128]); add2(aR[op+1],  rs[1*128]);
                add2(aZ[op],  rs[2*128]); add2(aZ[op+1],  rs[3*128]);
                add2(aGN[op], rs[4*128]); add2(aGN[op+1], rs[5*128]);
                add2(aIN[op], rs[6*128]); add2(aIN[op+1], rs[7*128]);
            }

            float fR[4], fZ[4], fGN[4], fIN[4];
            float2 v;
            v = up2(aR[op]);    fR[0]=v.x;  fR[1]=v.y;
            v = up2(aR[op+1]);  fR[2]=v.x;  fR[3]=v.y;
            v = up2(aZ[op]);    fZ[0]=v.x;  fZ[1]=v.y;
            v = up2(aZ[op+1]);  fZ[2]=v.x;  fZ[3]=v.y;
            v = up2(aGN[op]);   fGN[0]=v.x; fGN[1]=v.y;
            v = up2(aGN[op+1]); fGN[2]=v.x; fGN[3]=v.y;
            v = up2(aIN[op]);   fIN[0]=v.x; fIN[1]=v.y;
            v = up2(aIN[op+1]); fIN[2]=v.x; fIN[3]=v.y;

            float hNew[4], hdN[4];
            #pragma unroll
            for (int lb = 0; lb < 4; lb++) {
                float r = sigf(fR[lb] + bihr + bhhr);
                float z = sigf(fZ[lb] + bihz + bhhz);
                float n = tanhfast(fIN[lb] + bihn + r * (fGN[lb] + bhhn));
                hNew[lb] = n + z * (hdecP[lb] - n);
                float g = __expf(-fmaxf(dtn[lb] * dhwj + dhbj, 0.f));
                hdN[lb] = hNew[lb] * g;
                hdecP[lb] = hdN[lb];
            }
            *(float4*)(sh_hd + j*8 + half*4) = make_float4(hdN[0],hdN[1],hdN[2],hdN[3]);
            if (t + 1 < T_ && tid < 48) {
                bool obs = (mm_n > 0.5f);
                running = obs ? 0.f : (running + dtv_n);
                float gx = __expf(-fmaxf(running * axw + axb, 0.f));
                xlast = obs ? xv_n : xlast;
                float xhat = mm_n*xv_n + (1.f-mm_n)*(gx*xlast + (1.f-gx)*xm);
                sh_gin[ac*8 + ab]     = xhat;
                sh_gin[(6+ac)*8 + ab] = mm_n;
            }

            BAR_SYNC(EMPTY0 + s);
            *(float4*)(smem + OFF_H + s*1024 + j*8 + half*4) = make_float4(hNew[0],hNew[1],hNew[2],hNew[3]);
            asm volatile("membar.cta;" ::: "memory");
            BAR_ARRIVE(FULL0 + s);
        }
    } else {
        // ================= HEAD GROUP: consumer =============================
        BAR_ARRIVE(EMPTY0 + 0);
        BAR_ARRIVE(EMPTY0 + 1);

        for (int tt = 0; tt < T_; ++tt) {
            const int s = tt & 1;
            BAR_SYNC(FULL0 + s);
            const float* sh_hc = smem + OFF_H + s*1024;

            ull aP[4], aU[4];
            #pragma unroll
            for (int p = 0; p < 4; p++) { aP[p]=0; aU[p]=0; }

            // pair macros: 2 rows per invocation
            #define PROW2(PP) do {                                           \
                float2 w2v = __ldg((const float2*)g_w1T2f + (PP)*H_ + hj);   \
                int k = 2*(PP);                                              \
                ulonglong2 hA0 = *(const ulonglong2*)(sh_hc + k*8);          \
                ulonglong2 hB0 = *(const ulonglong2*)(sh_hc + k*8 + 4);      \
                ulonglong2 hA1 = *(const ulonglong2*)(sh_hc + k*8 + 8);      \
                ulonglong2 hB1 = *(const ulonglong2*)(sh_hc + k*8 + 12);     \
                ull wp0 = pk2(w2v.x, w2v.x), wp1 = pk2(w2v.y, w2v.y);        \
                fma2(aP[0],hA0.x,wp0); fma2(aP[1],hA0.y,wp0);                \
                fma2(aP[2],hB0.x,wp0); fma2(aP[3],hB0.y,wp0);                \
                fma2(aP[0],hA1.x,wp1); fma2(aP[1],hA1.y,wp1);                \
                fma2(aP[2],hB1.x,wp1); fma2(aP[3],hB1.y,wp1);                \
            } while (0)
            #define PUROW2(PP) do {                                          \
                float2 w2v = __ldg((const float2*)g_w1T2f + (PP)*H_ + hj);   \
                float2 wuv = __ldg((const float2*)g_wu1T2f + (PP)*64 + u);   \
                int k = 2*(PP);                                              \
                ulonglong2 hA0 = *(const ulonglong2*)(sh_hc + k*8);          \
                ulonglong2 hB0 = *(const ulonglong2*)(sh_hc + k*8 + 4);      \
                ulonglong2 hA1 = *(const ulonglong2*)(sh_hc + k*8 + 8);      \
                ulonglong2 hB1 = *(const ulonglong2*)(sh_hc + k*8 + 12);     \
                ull wp0 = pk2(w2v.x, w2v.x), wp1 = pk2(w2v.y, w2v.y);        \
                ull wu0 = pk2(wuv.x, wuv.x), wu1_ = pk2(wuv.y, wuv.y);       \
                fma2(aP[0],hA0.x,wp0); fma2(aP[1],hA0.y,wp0);                \
                fma2(aP[2],hB0.x,wp0); fma2(aP[3],hB0.y,wp0);                \
                fma2(aU[0],hA0.x,wu0); fma2(aU[1],hA0.y,wu0);                \
                fma2(aU[2],hB0.x,wu0); fma2(aU[3],hB0.y,wu0);                \
                fma2(aP[0],hA1.x,wp1); fma2(aP[1],hA1.y,wp1);                \
                fma2(aP[2],hB1.x,wp1); fma2(aP[3],hB1.y,wp1);                \
                fma2(aU[0],hA1.x,wu1_);fma2(aU[1],hA1.y,wu1_);               \
                fma2(aU[2],hB1.x,wu1_);fma2(aU[3],hB1.y,wu1_);               \
            } while (0)

            if (khalf == 0) {
                #pragma unroll 4
                for (int p = 0; p < 32; p++)  PUROW2(p);
                #pragma unroll 4
                for (int p = 32; p < 64; p++) PROW2(p);
            } else {
                #pragma unroll 4
                for (int p = 0; p < 32; p++)  PROW2(p);
                #pragma unroll 4
                for (int p = 32; p < 64; p++) PUROW2(p);
            }
            #undef PROW2
            #undef PUROW2

            BAR_ARRIVE(EMPTY0 + s);

            {
                float2 v;
                #pragma unroll
                for (int p = 0; p < 4; p++) {
                    v = up2(aP[p]);
                    sh_hid1[(2*p  )*H_ + hj] = fmaxf(v.x + b1h, 0.f);
                    sh_hid1[(2*p+1)*H_ + hj] = fmaxf(v.y + b1h, 0.f);
                }
            }
            if (khalf == 1) {
                #pragma unroll
                for (int p = 0; p < 4; p++) s_up[p*64 + u] = aU[p];
            }
            BARH();
            ull uin[4];
            if (khalf == 0) {
                #pragma unroll
                for (int p = 0; p < 4; p++) uin[p] = s_up[p*64 + u];
            }
            BARH();
            if (khalf == 0) {
                float2 v;
                #pragma unroll
                for (int p = 0; p < 4; p++) {
                    add2(aU[p], uin[p]);
                    v = up2(aU[p]);
                    sh_hidu[(2*p  )*64 + u] = fmaxf(v.x + bu1u, 0.f);
                    sh_hidu[(2*p+1)*64 + u] = fmaxf(v.y + bu1u, 0.f);
                }
            }
            if (hj < 48) {
                float acc = b2c;
                const float* wrow = w2 + pc * H_;
                const float* hrow = sh_hid1 + pb * H_;
                #pragma unroll 4
                for (int k = 0; k < H_; k += 4) {
                    float4 hh = *(const float4*)(hrow + k);
                    float4 ww = *(const float4*)(wrow + k);
                    acc += hh.x*ww.x + hh.y*ww.y + hh.z*ww.z + hh.w*ww.w;
                }
                out[((size_t)(b0 + pb) * T_ + tt) * C_ + pc] = acc;
            }
            BARH();
            if (vi >= 0 && vi < 48) {
                float acc = bu2c;
                const float* wrow = wu2 + uc * 64;
                const float* hrow = sh_hidu + ub * 64;
                #pragma unroll 4
                for (int k = 0; k < 64; k += 4) {
                    float4 hh = *(const float4*)(hrow + k);
                    float4 ww = *(const float4*)(wrow + k);
                    acc += hh.x*ww.x + hh.y*ww.y + hh.z*ww.z + hh.w*ww.w;
                }
                float sp = fmaxf(acc, 0.f) + log1pf(__expf(-fabsf(acc)));
                out[(size_t)B_*T_*C_ + ((size_t)(b0 + ub) * T_ + tt) * C_ + uc] = sp;
            }
        }
    }
}

extern "C" void kernel_launch(void* const* d_in, const int* in_sizes, int n_in,
                              void* d_out, int out_size) {
    const float* x      = (const float*)d_in[0];
    const float* x_mean = (const float*)d_in[1];
    const float* dxw    = (const float*)d_in[2];
    const float* dxb    = (const float*)d_in[3];
    const float* dhw    = (const float*)d_in[4];
    const float* dhb    = (const float*)d_in[5];
    const float* w_ih   = (const float*)d_in[6];
    const float* w_hh   = (const float*)d_in[7];
    const float* b_ih   = (const float*)d_in[8];
    const float* b_hh   = (const float*)d_in[9];
    const float* w1     = (const float*)d_in[10];
    const float* b1     = (const float*)d_in[11];
    const float* w2     = (const float*)d_in[12];
    const float* b2     = (const float*)d_in[13];
    const float* wu1    = (const float*)d_in[14];
    const float* bu1    = (const float*)d_in[15];
    const float* wu2    = (const float*)d_in[16];
    const float* bu2    = (const float*)d_in[17];
    float* out = (float*)d_out;

    // idempotent, not stream-captured; no static guards
    cudaFuncSetAttribute(grud_kernel, cudaFuncAttributeMaxDynamicSharedMemorySize, SMEM_BYTES);

    pack_kernel<<<NCTA, 128>>>(w_ih, w_hh, w1, wu1);
    grud_kernel<<<NCTA, NTHR, SMEM_BYTES>>>(x, x_mean, dxw, dxb, dhw, dhb,
                                            b_ih, b_hh, b1, w2, b2, bu1, wu2, bu2, out);
}